// round 15
// baseline (speedup 1.0000x reference)
#include <cuda_runtime.h>
#include <cuda_bf16.h>
#include <cstdint>

// Shapes (fixed by the problem)
#define BSZ    2
#define NN     384
#define DATOM  512
#define DPAIR  128
#define DHID   32
#define NROWS  (BSZ*NN)          // 768
#define PSLICE (NROWS*64)        // 49152
#define NSLICE 8                 // split-k slices (64 k each)

// Scratch (no cudaMalloc allowed)
__device__ float g_ab[NROWS * 64];            // bv half used by stage3 (cols 32..63)
__device__ float g_t [NROWS * DPAIR * DHID];  // t[row][p][y] (tf32-rounded bits)
__device__ float g_part[NSLICE * PSLICE];     // stage1 split-k partials

// ---------------- f32x2 packed-FMA helpers (sm_103a) ----------------
__device__ __forceinline__ unsigned long long pack2(float x, float y) {
    unsigned long long r;
    asm("mov.b64 %0,{%1,%2};" : "=l"(r) : "f"(x), "f"(y));
    return r;
}
__device__ __forceinline__ void unpack2(unsigned long long v, float& x, float& y) {
    asm("mov.b64 {%0,%1},%2;" : "=f"(x), "=f"(y) : "l"(v));
}
__device__ __forceinline__ void fma2(unsigned long long& d,
                                     unsigned long long a,
                                     unsigned long long b) {
    asm("fma.rn.f32x2 %0,%1,%2,%0;" : "+l"(d) : "l"(a), "l"(b));
}

// ---------------- tf32 / async helpers ----------------
__device__ __forceinline__ uint32_t f2tf32(float f) {
    uint32_t u;
    asm("cvt.rna.tf32.f32 %0, %1;" : "=r"(u) : "f"(f));
    return u;
}
__device__ __forceinline__ void mma_tf32(float c[4], const uint32_t a[4],
                                         const uint32_t b[2]) {
    asm("mma.sync.aligned.m16n8k8.row.col.f32.tf32.tf32.f32 "
        "{%0,%1,%2,%3}, {%4,%5,%6,%7}, {%8,%9}, {%0,%1,%2,%3};"
        : "+f"(c[0]), "+f"(c[1]), "+f"(c[2]), "+f"(c[3])
        : "r"(a[0]), "r"(a[1]), "r"(a[2]), "r"(a[3]), "r"(b[0]), "r"(b[1]));
}
__device__ __forceinline__ uint32_t smem_u32(const void* p) {
    uint32_t a;
    asm("{ .reg .u64 t; cvta.to.shared.u64 t, %1; cvt.u32.u64 %0, t; }" : "=r"(a) : "l"(p));
    return a;
}
#define CP_ASYNC16(dst, src) \
    asm volatile("cp.async.ca.shared.global [%0], [%1], 16;" :: "r"(dst), "l"(src))
#define CP_COMMIT() asm volatile("cp.async.commit_group;")
#define CP_WAIT0()  asm volatile("cp.async.wait_group 0;")

// ---------------- Stage 1a: split-k partial GEMM (16 rows/CTA, cp.async fills) ----------------
// grid (48 rowtiles, 8 kslices), block 256. Block: 16 rows x 64 h x 64 k.
// Each thread: 4 rows (rg, rg+4, rg+8, rg+12) -> w_s reads amortized 4x.
__global__ __launch_bounds__(256) void stage1a(
    const float* __restrict__ m, const float* __restrict__ W_in)
{
    __shared__ __align__(16) float m_s[16 * 64];     // 4 KB
    __shared__ __align__(16) float w_s[64 * 68];     // 17.4 KB (pad 68)
    int tid = threadIdx.x;
    int rbase = blockIdx.x * 16;
    int kc = blockIdx.y * 64;

    uint32_t ms_base = smem_u32(m_s);
    uint32_t ws_base = smem_u32(w_s);

    // m: 16 rows x 64 floats = 256 16B-segments (one per thread)
    {
        int r = tid >> 4, c = (tid & 15) * 4;
        CP_ASYNC16(ms_base + (uint32_t)(r * 64 + c) * 4,
                   m + (size_t)(rbase + r) * 512 + kc + c);
    }
    // W: 64 h x 64 floats = 1024 segments (4 per thread), padded rows
#pragma unroll
    for (int k = 0; k < 4; k++) {
        int idx4 = tid + k * 256;
        int h = idx4 >> 4, c = (idx4 & 15) * 4;
        CP_ASYNC16(ws_base + (uint32_t)(h * 68 + c) * 4,
                   W_in + (size_t)h * 512 + kc + c);
    }
    CP_COMMIT();
    CP_WAIT0();
    __syncthreads();

    int h = tid & 63, rg = tid >> 6;   // rows rg, rg+4, rg+8, rg+12
    unsigned long long acc[4] = {0ull, 0ull, 0ull, 0ull};
#pragma unroll
    for (int x = 0; x < 16; x++) {
        ulonglong2 wv = *(const ulonglong2*)&w_s[h * 68 + x * 4];   // conflict-free
#pragma unroll
        for (int rr = 0; rr < 4; rr++) {
            ulonglong2 mv = *(const ulonglong2*)&m_s[(rg + rr * 4) * 64 + x * 4]; // broadcast
            fma2(acc[rr], wv.x, mv.x);
            fma2(acc[rr], wv.y, mv.y);
        }
    }
    float* dst = g_part + (size_t)blockIdx.y * PSLICE;
#pragma unroll
    for (int rr = 0; rr < 4; rr++) {
        float lo, hi; unpack2(acc[rr], lo, hi);
        dst[(size_t)(rbase + rg + rr * 4) * 64 + h] = lo + hi;
    }
}

// ---------------- Stage 2 (fused reduce): t[row,p,y] = sum_x a[row,x]*Wo[p,x,y] ----------------
// grid (16 p-tiles, 24 row-tiles), block 256. Block: 8 p x 32 rows x 32 y.
// Reduces g_part (8 slices) -> a_s internally; blockIdx.x==0 also writes bv to g_ab.
__global__ __launch_bounds__(256) void stage2_t(
    const float* __restrict__ W_out, const float* __restrict__ b_in,
    const float* __restrict__ op_mask)
{
    __shared__ __align__(16) float w_s[8 * 1024];    // 32 KB
    __shared__ __align__(16) float a_s[32 * 32];
    int tid = threadIdx.x;
    int pbase = blockIdx.x * 8;
    int rbase = blockIdx.y * 32;

    const float4* wsrc = (const float4*)(W_out + (size_t)pbase * 1024);
    float4* wdst = (float4*)w_s;
#pragma unroll
    for (int k = 0; k < 8; k++) wdst[tid + k * 256] = wsrc[tid + k * 256];

    // a-half reduce: 32 rows x 32 cols over 8 slices
#pragma unroll
    for (int k = 0; k < 4; k++) {
        int e = tid + k * 256;           // 0..1023
        int r = e >> 5, c = e & 31;
        int gi = (rbase + r) * 64 + c;
        float s = 0.f;
#pragma unroll
        for (int sl = 0; sl < NSLICE; sl++) s += g_part[gi + sl * PSLICE];
        a_s[r * 32 + c] = (s + b_in[c]) * op_mask[rbase + r];
    }
    // bv-half reduce + write (one block column only)
    if (blockIdx.x == 0) {
#pragma unroll
        for (int k = 0; k < 4; k++) {
            int e = tid + k * 256;
            int r = e >> 5, c = e & 31;
            int gi = (rbase + r) * 64 + 32 + c;
            float s = 0.f;
#pragma unroll
            for (int sl = 0; sl < NSLICE; sl++) s += g_part[gi + sl * PSLICE];
            g_ab[gi] = (s + b_in[32 + c]) * op_mask[rbase + r];
        }
    }
    __syncthreads();

    int y = tid & 31, q = tid >> 5;      // lane=y, warp=p-within-tile (8 p)
    unsigned long long w2[16];
#pragma unroll
    for (int x2 = 0; x2 < 16; x2++) {
        w2[x2] = pack2(w_s[q * 1024 + (2 * x2 + 0) * 32 + y],
                       w_s[q * 1024 + (2 * x2 + 1) * 32 + y]);
    }
    float* dst = g_t + (size_t)rbase * 4096 + (size_t)(pbase + q) * 32 + y;
#pragma unroll 4
    for (int r = 0; r < 32; r++) {
        unsigned long long acc = 0ull;
#pragma unroll
        for (int xc = 0; xc < 8; xc++) {
            ulonglong2 a2 = *(const ulonglong2*)&a_s[r * 32 + xc * 4]; // broadcast
            fma2(acc, a2.x, w2[2 * xc + 0]);
            fma2(acc, a2.y, w2[2 * xc + 1]);
        }
        float lo, hi; unpack2(acc, lo, hi);
        dst[(size_t)r * 4096] = __uint_as_float(f2tf32(lo + hi));
    }
}

// ---------------- Stage 3 (warp MMA, tf32, cp.async pipelined) — exact R6/R10 ----------------
// grid (2, NN, BSZ): each CTA = 3 j-chunks of 64 for one (b,i).
// Warp grid 2(j) x 4(p): warp tile 32j x 32p. a_s double-buffered via cp.async.
#define S3PAD 36
__global__ __launch_bounds__(256, 3) void stage3_mma(
    const float* __restrict__ b_out, const float* __restrict__ op_norm,
    float* __restrict__ out)
{
    __shared__ __align__(16) uint32_t t_s[128 * S3PAD];     // 18.4 KB (tf32 bits)
    __shared__ __align__(16) uint32_t a_s[2][64 * S3PAD];   // 2 x 9.2 KB (raw fp32 bv)
    __shared__ float bo_s[128];

    int tid = threadIdx.x;
    int half = blockIdx.x;        // 0/1: j-chunks 0..2 / 3..5
    int i = blockIdx.y;
    int b = blockIdx.z;
    int row = b * NN + i;

    uint32_t t_base = smem_u32(t_s);
    uint32_t a_base = smem_u32(a_s);

    // async fill t row (16 KB, already tf32-rounded by stage2)
    const float* tsrc = g_t + (size_t)row * 4096;
#pragma unroll
    for (int k = 0; k < 4; k++) {
        int idx4 = tid + k * 256;
        int e = idx4 * 4, p = e >> 5, y = e & 31;
        CP_ASYNC16(t_base + (uint32_t)(p * S3PAD + y) * 4, tsrc + e);
    }
    // async fill a_s buf0 (chunk 0 of this half): raw fp32 bv
    const float* absrc = g_ab + (size_t)(b * NN) * 64;
    int jb0 = half * 192;
#pragma unroll
    for (int k = 0; k < 2; k++) {
        int idx4 = tid + k * 256;
        int j = idx4 >> 3, c = (idx4 & 7) * 4;
        CP_ASYNC16(a_base + (uint32_t)(j * S3PAD + c) * 4,
                   absrc + (size_t)(jb0 + j) * 64 + 32 + c);
    }
    CP_COMMIT();
    if (tid < 128) bo_s[tid] = b_out[tid];

    int wid = tid >> 5, lane = tid & 31;
    int g = lane >> 2, tg = lane & 3;
    int wm = wid & 1;          // j block of 32 (within 64-chunk)
    int wn = wid >> 1;         // p block of 32
    float norm = op_norm[b];

    for (int jc = 0; jc < 3; jc++) {
        int jbase = half * 192 + jc * 64;
        int buf = jc & 1;
        CP_WAIT0();
        __syncthreads();   // buf ready; all warps done with prev chunk (other buf)

        if (jc < 2) {      // prefetch next chunk into other buffer
            uint32_t dstb = a_base + (uint32_t)((buf ^ 1) * 64 * S3PAD) * 4;
#pragma unroll
            for (int k = 0; k < 2; k++) {
                int idx4 = tid + k * 256;
                int j = idx4 >> 3, c = (idx4 & 7) * 4;
                CP_ASYNC16(dstb + (uint32_t)(j * S3PAD + c) * 4,
                           absrc + (size_t)(jbase + 64 + j) * 64 + 32 + c);
            }
            CP_COMMIT();
        } else {
            CP_COMMIT();   // keep wait_group balanced
        }

        const uint32_t* ab = a_s[buf];
        float acc[2][4][4];
#pragma unroll
        for (int mt = 0; mt < 2; mt++)
#pragma unroll
            for (int nt = 0; nt < 4; nt++)
#pragma unroll
                for (int r = 0; r < 4; r++) acc[mt][nt][r] = 0.f;

#pragma unroll
        for (int ks = 0; ks < 4; ks++) {
            int kk = ks * 8;
            uint32_t af[2][4];
#pragma unroll
            for (int mt = 0; mt < 2; mt++) {
                int r0 = wm * 32 + mt * 16;
                af[mt][0] = f2tf32(__uint_as_float(ab[(r0 + g) * S3PAD + kk + tg]));
                af[mt][1] = f2tf32(__uint_as_float(ab[(r0 + 8 + g) * S3PAD + kk + tg]));
                af[mt][2] = f2tf32(__uint_as_float(ab[(r0 + g) * S3PAD + kk + tg + 4]));
                af[mt][3] = f2tf32(__uint_as_float(ab[(r0 + 8 + g) * S3PAD + kk + tg + 4]));
            }
            uint32_t bf[4][2];
#pragma unroll
            for (int nt = 0; nt < 4; nt++) {
                int cc = wn * 32 + nt * 8 + g;
                bf[nt][0] = t_s[cc * S3PAD + kk + tg];
                bf[nt][1] = t_s[cc * S3PAD + kk + tg + 4];
            }
#pragma unroll
            for (int mt = 0; mt < 2; mt++)
#pragma unroll
                for (int nt = 0; nt < 4; nt++)
                    mma_tf32(acc[mt][nt], af[mt], bf[nt]);
        }

        // epilogue: z = acc*norm + b_out[p]*norm (streaming stores)
        size_t obase = ((size_t)row * NN + jbase) * DPAIR;
#pragma unroll
        for (int mt = 0; mt < 2; mt++) {
            int j0 = wm * 32 + mt * 16 + g;
#pragma unroll
            for (int nt = 0; nt < 4; nt++) {
                int p = wn * 32 + nt * 8 + 2 * tg;
                float bz0 = bo_s[p] * norm, bz1 = bo_s[p + 1] * norm;
                float2 v0 = make_float2(fmaf(acc[mt][nt][0], norm, bz0),
                                        fmaf(acc[mt][nt][1], norm, bz1));
                float2 v1 = make_float2(fmaf(acc[mt][nt][2], norm, bz0),
                                        fmaf(acc[mt][nt][3], norm, bz1));
                __stcs((float2*)(out + obase + (size_t)j0 * DPAIR + p), v0);
                __stcs((float2*)(out + obase + (size_t)(j0 + 8) * DPAIR + p), v1);
            }
        }
    }
}

// ---------------- launch ----------------
extern "C" void kernel_launch(void* const* d_in, const int* in_sizes, int n_in,
                              void* d_out, int out_size)
{
    const float* m       = (const float*)d_in[0];
    const float* op_mask = (const float*)d_in[1];
    const float* op_norm = (const float*)d_in[2];
    const float* W_in    = (const float*)d_in[3];
    const float* b_in    = (const float*)d_in[4];
    const float* W_out   = (const float*)d_in[5];
    const float* b_out   = (const float*)d_in[6];
    float* out = (float*)d_out;

    stage1a<<<dim3(48, NSLICE), 256>>>(m, W_in);
    stage2_t<<<dim3(16, 24), 256>>>(W_out, b_in, op_mask);
    stage3_mma<<<dim3(2, NN, BSZ), 256>>>(b_out, op_norm, out);
}

// round 16
// speedup vs baseline: 1.0594x; 1.0594x over previous
#include <cuda_runtime.h>
#include <cuda_bf16.h>
#include <cstdint>

// Shapes (fixed by the problem)
#define BSZ    2
#define NN     384
#define DATOM  512
#define DPAIR  128
#define DHID   32
#define NROWS  (BSZ*NN)          // 768
#define PSLICE (NROWS*64)        // 49152
#define NSLICE 8                 // split-k slices (64 k each)

// Scratch (no cudaMalloc allowed)
__device__ float g_ab[NROWS * 64];            // bv half (cols 32..63) PRE-ROUNDED tf32
__device__ float g_t [NROWS * DPAIR * DHID];  // t[row][p][y] (tf32-rounded bits)
__device__ float g_part[NSLICE * PSLICE];     // stage1 split-k partials

// ---------------- f32x2 packed-FMA helpers (sm_103a) ----------------
__device__ __forceinline__ unsigned long long pack2(float x, float y) {
    unsigned long long r;
    asm("mov.b64 %0,{%1,%2};" : "=l"(r) : "f"(x), "f"(y));
    return r;
}
__device__ __forceinline__ void unpack2(unsigned long long v, float& x, float& y) {
    asm("mov.b64 {%0,%1},%2;" : "=f"(x), "=f"(y) : "l"(v));
}
__device__ __forceinline__ void fma2(unsigned long long& d,
                                     unsigned long long a,
                                     unsigned long long b) {
    asm("fma.rn.f32x2 %0,%1,%2,%0;" : "+l"(d) : "l"(a), "l"(b));
}

// ---------------- tf32 / async helpers ----------------
__device__ __forceinline__ uint32_t f2tf32(float f) {
    uint32_t u;
    asm("cvt.rna.tf32.f32 %0, %1;" : "=r"(u) : "f"(f));
    return u;
}
__device__ __forceinline__ void mma_tf32(float c[4], const uint32_t a[4],
                                         const uint32_t b[2]) {
    asm("mma.sync.aligned.m16n8k8.row.col.f32.tf32.tf32.f32 "
        "{%0,%1,%2,%3}, {%4,%5,%6,%7}, {%8,%9}, {%0,%1,%2,%3};"
        : "+f"(c[0]), "+f"(c[1]), "+f"(c[2]), "+f"(c[3])
        : "r"(a[0]), "r"(a[1]), "r"(a[2]), "r"(a[3]), "r"(b[0]), "r"(b[1]));
}
__device__ __forceinline__ uint32_t smem_u32(const void* p) {
    uint32_t a;
    asm("{ .reg .u64 t; cvta.to.shared.u64 t, %1; cvt.u32.u64 %0, t; }" : "=r"(a) : "l"(p));
    return a;
}
#define CP_ASYNC16(dst, src) \
    asm volatile("cp.async.ca.shared.global [%0], [%1], 16;" :: "r"(dst), "l"(src))
#define CP_COMMIT() asm volatile("cp.async.commit_group;")
#define CP_WAIT0()  asm volatile("cp.async.wait_group 0;")

// ---------------- Stage 1a: split-k partial GEMM (16 rows/CTA, cp.async fills) ----------------
// grid (48 rowtiles, 8 kslices), block 256. Block: 16 rows x 64 h x 64 k.
__global__ __launch_bounds__(256) void stage1a(
    const float* __restrict__ m, const float* __restrict__ W_in)
{
    __shared__ __align__(16) float m_s[16 * 64];     // 4 KB
    __shared__ __align__(16) float w_s[64 * 68];     // 17.4 KB (pad 68)
    int tid = threadIdx.x;
    int rbase = blockIdx.x * 16;
    int kc = blockIdx.y * 64;

    uint32_t ms_base = smem_u32(m_s);
    uint32_t ws_base = smem_u32(w_s);

    {
        int r = tid >> 4, c = (tid & 15) * 4;
        CP_ASYNC16(ms_base + (uint32_t)(r * 64 + c) * 4,
                   m + (size_t)(rbase + r) * 512 + kc + c);
    }
#pragma unroll
    for (int k = 0; k < 4; k++) {
        int idx4 = tid + k * 256;
        int h = idx4 >> 4, c = (idx4 & 15) * 4;
        CP_ASYNC16(ws_base + (uint32_t)(h * 68 + c) * 4,
                   W_in + (size_t)h * 512 + kc + c);
    }
    CP_COMMIT();
    CP_WAIT0();
    __syncthreads();

    int h = tid & 63, rg = tid >> 6;   // rows rg, rg+4, rg+8, rg+12
    unsigned long long acc[4] = {0ull, 0ull, 0ull, 0ull};
#pragma unroll
    for (int x = 0; x < 16; x++) {
        ulonglong2 wv = *(const ulonglong2*)&w_s[h * 68 + x * 4];   // conflict-free
#pragma unroll
        for (int rr = 0; rr < 4; rr++) {
            ulonglong2 mv = *(const ulonglong2*)&m_s[(rg + rr * 4) * 64 + x * 4]; // broadcast
            fma2(acc[rr], wv.x, mv.x);
            fma2(acc[rr], wv.y, mv.y);
        }
    }
    float* dst = g_part + (size_t)blockIdx.y * PSLICE;
#pragma unroll
    for (int rr = 0; rr < 4; rr++) {
        float lo, hi; unpack2(acc[rr], lo, hi);
        dst[(size_t)(rbase + rg + rr * 4) * 64 + h] = lo + hi;
    }
}

// ---------------- Stage 2 (fused reduce): t[row,p,y] = sum_x a[row,x]*Wo[p,x,y] ----------------
// grid (16 p-tiles, 24 row-tiles), block 256. Block: 8 p x 32 rows x 32 y.
// Reduces g_part (8 slices) -> a_s internally; blockIdx.x==0 also writes bv
// (PRE-ROUNDED to tf32) to g_ab for stage3.
__global__ __launch_bounds__(256) void stage2_t(
    const float* __restrict__ W_out, const float* __restrict__ b_in,
    const float* __restrict__ op_mask)
{
    __shared__ __align__(16) float w_s[8 * 1024];    // 32 KB
    __shared__ __align__(16) float a_s[32 * 32];
    int tid = threadIdx.x;
    int pbase = blockIdx.x * 8;
    int rbase = blockIdx.y * 32;

    const float4* wsrc = (const float4*)(W_out + (size_t)pbase * 1024);
    float4* wdst = (float4*)w_s;
#pragma unroll
    for (int k = 0; k < 8; k++) wdst[tid + k * 256] = wsrc[tid + k * 256];

    // a-half reduce: 32 rows x 32 cols over 8 slices
#pragma unroll
    for (int k = 0; k < 4; k++) {
        int e = tid + k * 256;           // 0..1023
        int r = e >> 5, c = e & 31;
        int gi = (rbase + r) * 64 + c;
        float s = 0.f;
#pragma unroll
        for (int sl = 0; sl < NSLICE; sl++) s += g_part[gi + sl * PSLICE];
        a_s[r * 32 + c] = (s + b_in[c]) * op_mask[rbase + r];
    }
    // bv-half reduce + write, pre-rounded to tf32 (one block column only)
    if (blockIdx.x == 0) {
#pragma unroll
        for (int k = 0; k < 4; k++) {
            int e = tid + k * 256;
            int r = e >> 5, c = e & 31;
            int gi = (rbase + r) * 64 + 32 + c;
            float s = 0.f;
#pragma unroll
            for (int sl = 0; sl < NSLICE; sl++) s += g_part[gi + sl * PSLICE];
            float val = (s + b_in[32 + c]) * op_mask[rbase + r];
            g_ab[gi] = __uint_as_float(f2tf32(val));
        }
    }
    __syncthreads();

    int y = tid & 31, q = tid >> 5;      // lane=y, warp=p-within-tile (8 p)
    unsigned long long w2[16];
#pragma unroll
    for (int x2 = 0; x2 < 16; x2++) {
        w2[x2] = pack2(w_s[q * 1024 + (2 * x2 + 0) * 32 + y],
                       w_s[q * 1024 + (2 * x2 + 1) * 32 + y]);
    }
    float* dst = g_t + (size_t)rbase * 4096 + (size_t)(pbase + q) * 32 + y;
#pragma unroll 4
    for (int r = 0; r < 32; r++) {
        unsigned long long acc = 0ull;
#pragma unroll
        for (int xc = 0; xc < 8; xc++) {
            ulonglong2 a2 = *(const ulonglong2*)&a_s[r * 32 + xc * 4]; // broadcast
            fma2(acc, a2.x, w2[2 * xc + 0]);
            fma2(acc, a2.y, w2[2 * xc + 1]);
        }
        float lo, hi; unpack2(acc, lo, hi);
        dst[(size_t)r * 4096] = __uint_as_float(f2tf32(lo + hi));
    }
}

// ---------------- Stage 3 (warp MMA, tf32, cp.async pipelined) — R6/R10 body ----------------
// grid (2, NN, BSZ): each CTA = 3 j-chunks of 64 for one (b,i).
// Warp grid 2(j) x 4(p): warp tile 32j x 32p. a_s double-buffered via cp.async.
// bv is pre-rounded tf32 in g_ab -> A fragments load raw (no cvt in mainloop).
#define S3PAD 36
__global__ __launch_bounds__(256, 3) void stage3_mma(
    const float* __restrict__ b_out, const float* __restrict__ op_norm,
    float* __restrict__ out)
{
    __shared__ __align__(16) uint32_t t_s[128 * S3PAD];     // 18.4 KB (tf32 bits)
    __shared__ __align__(16) uint32_t a_s[2][64 * S3PAD];   // 2 x 9.2 KB (tf32 bits)
    __shared__ float bo_s[128];

    int tid = threadIdx.x;
    int half = blockIdx.x;        // 0/1: j-chunks 0..2 / 3..5
    int i = blockIdx.y;
    int b = blockIdx.z;
    int row = b * NN + i;

    uint32_t t_base = smem_u32(t_s);
    uint32_t a_base = smem_u32(a_s);

    // async fill t row (16 KB, already tf32-rounded by stage2)
    const float* tsrc = g_t + (size_t)row * 4096;
#pragma unroll
    for (int k = 0; k < 4; k++) {
        int idx4 = tid + k * 256;
        int e = idx4 * 4, p = e >> 5, y = e & 31;
        CP_ASYNC16(t_base + (uint32_t)(p * S3PAD + y) * 4, tsrc + e);
    }
    // async fill a_s buf0 (chunk 0 of this half): tf32-rounded bv
    const float* absrc = g_ab + (size_t)(b * NN) * 64;
    int jb0 = half * 192;
#pragma unroll
    for (int k = 0; k < 2; k++) {
        int idx4 = tid + k * 256;
        int j = idx4 >> 3, c = (idx4 & 7) * 4;
        CP_ASYNC16(a_base + (uint32_t)(j * S3PAD + c) * 4,
                   absrc + (size_t)(jb0 + j) * 64 + 32 + c);
    }
    CP_COMMIT();
    if (tid < 128) bo_s[tid] = b_out[tid];

    int wid = tid >> 5, lane = tid & 31;
    int g = lane >> 2, tg = lane & 3;
    int wm = wid & 1;          // j block of 32 (within 64-chunk)
    int wn = wid >> 1;         // p block of 32
    float norm = op_norm[b];

    for (int jc = 0; jc < 3; jc++) {
        int jbase = half * 192 + jc * 64;
        int buf = jc & 1;
        CP_WAIT0();
        __syncthreads();   // buf ready; all warps done with prev chunk (other buf)

        if (jc < 2) {      // prefetch next chunk into other buffer
            uint32_t dstb = a_base + (uint32_t)((buf ^ 1) * 64 * S3PAD) * 4;
#pragma unroll
            for (int k = 0; k < 2; k++) {
                int idx4 = tid + k * 256;
                int j = idx4 >> 3, c = (idx4 & 7) * 4;
                CP_ASYNC16(dstb + (uint32_t)(j * S3PAD + c) * 4,
                           absrc + (size_t)(jbase + 64 + j) * 64 + 32 + c);
            }
            CP_COMMIT();
        } else {
            CP_COMMIT();   // keep wait_group balanced
        }

        const uint32_t* ab = a_s[buf];
        float acc[2][4][4];
#pragma unroll
        for (int mt = 0; mt < 2; mt++)
#pragma unroll
            for (int nt = 0; nt < 4; nt++)
#pragma unroll
                for (int r = 0; r < 4; r++) acc[mt][nt][r] = 0.f;

#pragma unroll
        for (int ks = 0; ks < 4; ks++) {
            int kk = ks * 8;
            uint32_t af[2][4];
#pragma unroll
            for (int mt = 0; mt < 2; mt++) {
                int r0 = wm * 32 + mt * 16;
                af[mt][0] = ab[(r0 + g) * S3PAD + kk + tg];
                af[mt][1] = ab[(r0 + 8 + g) * S3PAD + kk + tg];
                af[mt][2] = ab[(r0 + g) * S3PAD + kk + tg + 4];
                af[mt][3] = ab[(r0 + 8 + g) * S3PAD + kk + tg + 4];
            }
            uint32_t bf[4][2];
#pragma unroll
            for (int nt = 0; nt < 4; nt++) {
                int cc = wn * 32 + nt * 8 + g;
                bf[nt][0] = t_s[cc * S3PAD + kk + tg];
                bf[nt][1] = t_s[cc * S3PAD + kk + tg + 4];
            }
#pragma unroll
            for (int mt = 0; mt < 2; mt++)
#pragma unroll
                for (int nt = 0; nt < 4; nt++)
                    mma_tf32(acc[mt][nt], af[mt], bf[nt]);
        }

        // epilogue: z = acc*norm + b_out[p]*norm (streaming stores)
        size_t obase = ((size_t)row * NN + jbase) * DPAIR;
#pragma unroll
        for (int mt = 0; mt < 2; mt++) {
            int j0 = wm * 32 + mt * 16 + g;
#pragma unroll
            for (int nt = 0; nt < 4; nt++) {
                int p = wn * 32 + nt * 8 + 2 * tg;
                float bz0 = bo_s[p] * norm, bz1 = bo_s[p + 1] * norm;
                float2 v0 = make_float2(fmaf(acc[mt][nt][0], norm, bz0),
                                        fmaf(acc[mt][nt][1], norm, bz1));
                float2 v1 = make_float2(fmaf(acc[mt][nt][2], norm, bz0),
                                        fmaf(acc[mt][nt][3], norm, bz1));
                __stcs((float2*)(out + obase + (size_t)j0 * DPAIR + p), v0);
                __stcs((float2*)(out + obase + (size_t)(j0 + 8) * DPAIR + p), v1);
            }
        }
    }
}

// ---------------- launch ----------------
extern "C" void kernel_launch(void* const* d_in, const int* in_sizes, int n_in,
                              void* d_out, int out_size)
{
    const float* m       = (const float*)d_in[0];
    const float* op_mask = (const float*)d_in[1];
    const float* op_norm = (const float*)d_in[2];
    const float* W_in    = (const float*)d_in[3];
    const float* b_in    = (const float*)d_in[4];
    const float* W_out   = (const float*)d_in[5];
    const float* b_out   = (const float*)d_in[6];
    float* out = (float*)d_out;

    stage1a<<<dim3(48, NSLICE), 256>>>(m, W_in);
    stage2_t<<<dim3(16, 24), 256>>>(W_out, b_in, op_mask);
    stage3_mma<<<dim3(2, NN, BSZ), 256>>>(b_out, op_norm, out);
}